// round 1
// baseline (speedup 1.0000x reference)
#include <cuda_runtime.h>
#include <cuda_bf16.h>
#include <cstdint>

#define BB 4
#define HH 256
#define CC 80
#define TX 256
#define TY 1024
#define NEGV (-1e9f)

// Output layout (float32, concatenated in reference return order):
//  o_en_ex [B,H,Ty]  -> offset 0,        1048576 elems
//  logp    [B,Tx,Ty] -> offset 1048576,  1048576 elems
//  attn    [B,Tx,Ty] -> offset 2097152,  1048576 elems
//  dr_mas  [B,Tx]    -> offset 3145728,  1024 elems
#define OFF_OEN  0
#define OFF_LOGP 1048576
#define OFF_ATTN 2097152
#define OFF_DR   3145728

// -------- device scratch (no allocations allowed) --------
__device__ float g_A  [BB*CC*TX];   // -0.5/C * exp(-2 ls)
__device__ float g_Bc [BB*CC*TX];   //  1/C   * exp(-2 ls) * mu
__device__ float g_cst[BB*TX];      // -0.5/C * (sum w*mu^2 + sum ls)
__device__ float g_lpT[BB*TY*TX];   // masked logp, transposed [b][y][x]
__device__ int   g_idx[BB*TY];      // backtracked alignment (-1 = inactive y)

// =====================================================================
// K1: per-(b,x) channel precompute
// =====================================================================
__global__ void k_pre(const float* __restrict__ mu,
                      const float* __restrict__ ls) {
    int b = blockIdx.x;
    int x = threadIdx.x;
    float s3 = 0.f, sl = 0.f;
    #pragma unroll 4
    for (int c = 0; c < CC; c++) {
        int o = (b * CC + c) * TX + x;
        float l = ls[o];
        float m = mu[o];
        float w = expf(-2.0f * l);
        g_A [o] = (-0.5f / (float)CC) * w;
        g_Bc[o] = (1.0f / (float)CC) * w * m;
        s3 += w * m * m;
        sl += l;
    }
    g_cst[b * TX + x] = (-0.5f / (float)CC) * (s3 + sl);
}

// =====================================================================
// K2: logp GEMM  logp[b,x,y] = sum_c A*y^2 + B*y + cst
//     tile 64x64, C chunked by 40, 256 threads, 4x4 micro-tile
//     writes logp (output layout) + masked transposed copy for the DP
// =====================================================================
#define TSX 64
#define TSY 64
#define KCH 40

__global__ __launch_bounds__(256, 2)
void k_logp(const float* __restrict__ y,
            const int* __restrict__ xl,
            const int* __restrict__ yl,
            float* __restrict__ out) {
    __shared__ float sA [KCH][TSX];
    __shared__ float sB [KCH][TSX];
    __shared__ float sY [KCH][TSY];
    __shared__ float sY2[KCH][TSY];

    int b  = blockIdx.z;
    int x0 = blockIdx.y * TSX;
    int y0 = blockIdx.x * TSY;
    int tid = threadIdx.x;
    int ty = tid & 15;
    int tx = tid >> 4;
    int xr = tx * 4;
    int yc = ty * 4;

    float acc[4][4] = {};

    for (int kc = 0; kc < CC; kc += KCH) {
        __syncthreads();
        // load chunk: KCH*64 elems per array, 256 threads -> 10 each
        #pragma unroll
        for (int i = tid; i < KCH * TSX; i += 256) {
            int c = i >> 6, j = i & 63;
            int oa = (b * CC + (kc + c)) * TX + x0 + j;
            sA[c][j] = g_A[oa];
            sB[c][j] = g_Bc[oa];
            float yv = y[(b * CC + (kc + c)) * TY + y0 + j];
            sY [c][j] = yv;
            sY2[c][j] = yv * yv;
        }
        __syncthreads();

        #pragma unroll 8
        for (int c = 0; c < KCH; c++) {
            float4 a  = *(const float4*)&sA [c][xr];
            float4 bb = *(const float4*)&sB [c][xr];
            float4 yv = *(const float4*)&sY [c][yc];
            float4 y2 = *(const float4*)&sY2[c][yc];
            float av[4] = {a.x, a.y, a.z, a.w};
            float bv[4] = {bb.x, bb.y, bb.z, bb.w};
            float yvv[4] = {yv.x, yv.y, yv.z, yv.w};
            float y2v[4] = {y2.x, y2.y, y2.z, y2.w};
            #pragma unroll
            for (int i = 0; i < 4; i++)
                #pragma unroll
                for (int j = 0; j < 4; j++) {
                    acc[i][j] = fmaf(av[i], y2v[j], acc[i][j]);
                    acc[i][j] = fmaf(bv[i], yvv[j], acc[i][j]);
                }
        }
    }

    float cst_i[4];
    #pragma unroll
    for (int i = 0; i < 4; i++)
        cst_i[i] = g_cst[b * TX + x0 + xr + i];

    int xlen = xl[b], ylen = yl[b];

    // write logp (output layout [b][x][y])
    #pragma unroll
    for (int i = 0; i < 4; i++) {
        int gx = x0 + xr + i;
        float4 r;
        r.x = acc[i][0] + cst_i[i];
        r.y = acc[i][1] + cst_i[i];
        r.z = acc[i][2] + cst_i[i];
        r.w = acc[i][3] + cst_i[i];
        *(float4*)&out[OFF_LOGP + ((size_t)(b * TX + gx)) * TY + y0 + yc] = r;
    }

    // write masked transposed copy for the DP: g_lpT[b][y][x]
    #pragma unroll
    for (int j = 0; j < 4; j++) {
        int gy = y0 + yc + j;
        bool ym = gy < ylen;
        float4 t;
        t.x = (ym && (x0 + xr + 0) < xlen) ? acc[0][j] + cst_i[0] : NEGV;
        t.y = (ym && (x0 + xr + 1) < xlen) ? acc[1][j] + cst_i[1] : NEGV;
        t.z = (ym && (x0 + xr + 2) < xlen) ? acc[2][j] + cst_i[2] : NEGV;
        t.w = (ym && (x0 + xr + 3) < xlen) ? acc[3][j] + cst_i[3] : NEGV;
        *(float4*)&g_lpT[((size_t)(b * TY + gy)) * TX + x0 + xr] = t;
    }
}

// =====================================================================
// K3: Viterbi forward DP + backtrack, one block per batch
// =====================================================================
__global__ __launch_bounds__(256, 1)
void k_dp(const int* __restrict__ xl,
          const int* __restrict__ yl,
          float* __restrict__ out) {
    __shared__ unsigned s_diag[TY][TX / 32];   // 32 KB of packed diag bits
    __shared__ float    s_edge[2][8];          // parity-double-buffered warp edges
    __shared__ int      s_dr[TX];

    int b   = blockIdx.x;
    int tid = threadIdx.x;
    int lane = tid & 31;
    int wid  = tid >> 5;

    s_dr[tid] = 0;

    float v = (tid == 0) ? 0.0f : NEGV;
    const float* lpT = g_lpT + (size_t)b * TY * TX;

    for (int yy = 0; yy < TY; yy++) {
        float col = lpT[yy * TX + tid];              // coalesced column load
        float vs = __shfl_up_sync(0xffffffffu, v, 1);
        if (lane == 31) s_edge[yy & 1][wid] = v;
        __syncthreads();
        if (lane == 0) vs = (wid == 0) ? NEGV : s_edge[yy & 1][wid - 1];
        bool dg = vs > v;                            // come from (x-1, y-1)
        unsigned bal = __ballot_sync(0xffffffffu, dg);
        if (lane == 0) s_diag[yy][wid] = bal;
        v = col + fmaxf(v, vs);
    }
    __syncthreads();

    if (tid == 0) {
        int xlen = xl[b], ylen = yl[b];
        int idx = xlen - 1;
        for (int yy = TY - 1; yy >= 0; yy--) {
            if (yy < ylen) {
                g_idx[b * TY + yy] = idx;
                s_dr[idx]++;
                unsigned w = s_diag[yy][idx >> 5];
                if (idx > 0 && ((w >> (idx & 31)) & 1u)) idx--;
            } else {
                g_idx[b * TY + yy] = -1;
            }
        }
    }
    __syncthreads();

    out[OFF_DR + b * TX + tid] = (float)s_dr[tid];
}

// =====================================================================
// K4: attn one-hot expansion [b,x,y]
// =====================================================================
__global__ void k_attn(float* __restrict__ out) {
    int g = blockIdx.x * 256 + threadIdx.x;    // g over B*TX*TY
    int yy = g & (TY - 1);
    int x  = (g >> 10) & (TX - 1);
    int b  = g >> 18;
    out[OFF_ATTN + g] = (g_idx[b * TY + yy] == x) ? 1.0f : 0.0f;
}

// =====================================================================
// K5: o_en_ex gather  out[b,h,y] = en[b,h,idx(y)]  (path == attn for MAS)
// =====================================================================
__global__ void k_oen(const float* __restrict__ en,
                      float* __restrict__ out) {
    int g = blockIdx.x * 256 + threadIdx.x;    // g over B*H*TY
    int yy = g & (TY - 1);
    int h  = (g >> 10) & (HH - 1);
    int b  = g >> 18;
    int ix = g_idx[b * TY + yy];
    out[OFF_OEN + g] = (ix >= 0) ? en[(b * HH + h) * TX + ix] : 0.0f;
}

// =====================================================================
extern "C" void kernel_launch(void* const* d_in, const int* in_sizes, int n_in,
                              void* d_out, int out_size) {
    const float* en = (const float*)d_in[0];
    const float* mu = (const float*)d_in[1];
    const float* ls = (const float*)d_in[2];
    const float* y  = (const float*)d_in[3];
    const int*   xl = (const int*)d_in[4];
    const int*   yl = (const int*)d_in[5];
    float* out = (float*)d_out;

    k_pre<<<BB, TX>>>(mu, ls);

    dim3 g2(TY / TSY, TX / TSX, BB);   // (16, 4, 4)
    k_logp<<<g2, 256>>>(y, xl, yl, out);

    k_dp<<<BB, TX>>>(xl, yl, out);

    k_attn<<<(BB * TX * TY) / 256, 256>>>(out);
    k_oen <<<(BB * HH * TY) / 256, 256>>>(en, out);
}

// round 2
// speedup vs baseline: 1.7446x; 1.7446x over previous
#include <cuda_runtime.h>
#include <cuda_bf16.h>
#include <cstdint>

#define BB 4
#define HH 256
#define CC 80
#define TX 256
#define TY 1024
#define NEGV (-1e9f)

// Output layout (float32, concatenated in reference return order):
//  o_en_ex [B,H,Ty]  -> offset 0,        1048576 elems
//  logp    [B,Tx,Ty] -> offset 1048576,  1048576 elems
//  attn    [B,Tx,Ty] -> offset 2097152,  1048576 elems
//  dr_mas  [B,Tx]    -> offset 3145728,  1024 elems
#define OFF_OEN  0
#define OFF_LOGP 1048576
#define OFF_ATTN 2097152
#define OFF_DR   3145728

// -------- device scratch (no allocations allowed) --------
__device__ float g_A  [BB*CC*TX];   // -0.5/C * exp(-2 ls)
__device__ float g_Bc [BB*CC*TX];   //  1/C   * exp(-2 ls) * mu
__device__ float g_cst[BB*TX];      // -0.5/C * (sum w*mu^2 + sum ls)
__device__ float g_lpT[BB*TY*TX];   // masked logp, transposed [b][y][x]
__device__ int   g_idx[BB*TY];      // alignment index per y (-1 = inactive)

// =====================================================================
// K1: per-(b,x) channel precompute
// =====================================================================
__global__ void k_pre(const float* __restrict__ mu,
                      const float* __restrict__ ls) {
    int b = blockIdx.x;
    int x = threadIdx.x;
    float s3 = 0.f, sl = 0.f;
    #pragma unroll 4
    for (int c = 0; c < CC; c++) {
        int o = (b * CC + c) * TX + x;
        float l = ls[o];
        float m = mu[o];
        float w = expf(-2.0f * l);
        g_A [o] = (-0.5f / (float)CC) * w;
        g_Bc[o] = (1.0f / (float)CC) * w * m;
        s3 += w * m * m;
        sl += l;
    }
    g_cst[b * TX + x] = (-0.5f / (float)CC) * (s3 + sl);
}

// =====================================================================
// K2: logp GEMM  logp[b,x,y] = sum_c A*y^2 + B*y + cst
// =====================================================================
#define TSX 64
#define TSY 64
#define KCH 40

__global__ __launch_bounds__(256, 2)
void k_logp(const float* __restrict__ y,
            const int* __restrict__ xl,
            const int* __restrict__ yl,
            float* __restrict__ out) {
    __shared__ float sA [KCH][TSX];
    __shared__ float sB [KCH][TSX];
    __shared__ float sY [KCH][TSY];
    __shared__ float sY2[KCH][TSY];

    int b  = blockIdx.z;
    int x0 = blockIdx.y * TSX;
    int y0 = blockIdx.x * TSY;
    int tid = threadIdx.x;
    int ty = tid & 15;
    int tx = tid >> 4;
    int xr = tx * 4;
    int yc = ty * 4;

    float acc[4][4] = {};

    for (int kc = 0; kc < CC; kc += KCH) {
        __syncthreads();
        #pragma unroll
        for (int i = tid; i < KCH * TSX; i += 256) {
            int c = i >> 6, j = i & 63;
            int oa = (b * CC + (kc + c)) * TX + x0 + j;
            sA[c][j] = g_A[oa];
            sB[c][j] = g_Bc[oa];
            float yv = y[(b * CC + (kc + c)) * TY + y0 + j];
            sY [c][j] = yv;
            sY2[c][j] = yv * yv;
        }
        __syncthreads();

        #pragma unroll 8
        for (int c = 0; c < KCH; c++) {
            float4 a  = *(const float4*)&sA [c][xr];
            float4 bb = *(const float4*)&sB [c][xr];
            float4 yv = *(const float4*)&sY [c][yc];
            float4 y2 = *(const float4*)&sY2[c][yc];
            float av[4] = {a.x, a.y, a.z, a.w};
            float bv[4] = {bb.x, bb.y, bb.z, bb.w};
            float yvv[4] = {yv.x, yv.y, yv.z, yv.w};
            float y2v[4] = {y2.x, y2.y, y2.z, y2.w};
            #pragma unroll
            for (int i = 0; i < 4; i++)
                #pragma unroll
                for (int j = 0; j < 4; j++) {
                    acc[i][j] = fmaf(av[i], y2v[j], acc[i][j]);
                    acc[i][j] = fmaf(bv[i], yvv[j], acc[i][j]);
                }
        }
    }

    float cst_i[4];
    #pragma unroll
    for (int i = 0; i < 4; i++)
        cst_i[i] = g_cst[b * TX + x0 + xr + i];

    int xlen = xl[b], ylen = yl[b];

    #pragma unroll
    for (int i = 0; i < 4; i++) {
        int gx = x0 + xr + i;
        float4 r;
        r.x = acc[i][0] + cst_i[i];
        r.y = acc[i][1] + cst_i[i];
        r.z = acc[i][2] + cst_i[i];
        r.w = acc[i][3] + cst_i[i];
        *(float4*)&out[OFF_LOGP + ((size_t)(b * TX + gx)) * TY + y0 + yc] = r;
    }

    #pragma unroll
    for (int j = 0; j < 4; j++) {
        int gy = y0 + yc + j;
        bool ym = gy < ylen;
        float4 t;
        t.x = (ym && (x0 + xr + 0) < xlen) ? acc[0][j] + cst_i[0] : NEGV;
        t.y = (ym && (x0 + xr + 1) < xlen) ? acc[1][j] + cst_i[1] : NEGV;
        t.z = (ym && (x0 + xr + 2) < xlen) ? acc[2][j] + cst_i[2] : NEGV;
        t.w = (ym && (x0 + xr + 3) < xlen) ? acc[3][j] + cst_i[3] : NEGV;
        *(float4*)&g_lpT[((size_t)(b * TY + gy)) * TX + x0 + xr] = t;
    }
}

// =====================================================================
// K3: Viterbi DP — single warp per batch.
//   Forward: lane owns x in [lane*8, lane*8+8) in registers; one shfl/step.
//   Diag bits accumulated per-x in registers -> s_diagT[x][y/32].
//   Backtrack: run-length scan over bit words (~xlen iters, not Ty).
//   Then durations -> cumsum -> g_idx via parallel binary search.
// =====================================================================
__global__ __launch_bounds__(32, 1)
void k_dp(const int* __restrict__ xl,
          const int* __restrict__ yl,
          float* __restrict__ out) {
    __shared__ unsigned s_diagT[TX][TY / 32];   // 32 KB, bits over y per x
    __shared__ int s_dr[TX];
    __shared__ int s_cum[TX + 1];

    int b    = blockIdx.x;
    int lane = threadIdx.x;
    const float4* lp = (const float4*)(g_lpT + (size_t)b * TY * TX);
    const int ROWQ = TX / 4;     // 64 float4 per y-row

    #pragma unroll
    for (int i = 0; i < 8; i++) s_dr[lane * 8 + i] = 0;

    float v[8];
    #pragma unroll
    for (int i = 0; i < 8; i++) v[i] = NEGV;
    if (lane == 0) v[0] = 0.0f;

    unsigned dbits[8] = {0, 0, 0, 0, 0, 0, 0, 0};

    // prefetch pipeline, depth 8 steps (2 float4 per lane per step)
    float4 buf[8][2];
    #pragma unroll
    for (int p = 0; p < 8; p++) {
        buf[p][0] = lp[p * ROWQ + lane * 2];
        buf[p][1] = lp[p * ROWQ + lane * 2 + 1];
    }

    for (int y0 = 0; y0 < TY; y0 += 8) {
        unsigned bitbase = 1u << (y0 & 31);
        #pragma unroll
        for (int p = 0; p < 8; p++) {
            float c[8];
            c[0] = buf[p][0].x; c[1] = buf[p][0].y;
            c[2] = buf[p][0].z; c[3] = buf[p][0].w;
            c[4] = buf[p][1].x; c[5] = buf[p][1].y;
            c[6] = buf[p][1].z; c[7] = buf[p][1].w;

            // issue prefetch for step y0+p+8 immediately
            int ynext = y0 + p + 8;
            if (ynext < TY) {
                buf[p][0] = lp[ynext * ROWQ + lane * 2];
                buf[p][1] = lp[ynext * ROWQ + lane * 2 + 1];
            }

            float top = __shfl_up_sync(0xffffffffu, v[7], 1);
            if (lane == 0) top = NEGV;
            unsigned bit = bitbase << p;

            // update descending so v[i-1] is still the old value
            #pragma unroll
            for (int i = 7; i >= 1; i--) {
                if (v[i - 1] > v[i]) dbits[i] |= bit;
                v[i] = c[i] + fmaxf(v[i], v[i - 1]);
            }
            if (top > v[0]) dbits[0] |= bit;
            v[0] = c[0] + fmaxf(v[0], top);
        }
        if ((y0 & 31) == 24) {            // finished a 32-y word
            int w = y0 >> 5;
            #pragma unroll
            for (int i = 0; i < 8; i++) {
                s_diagT[lane * 8 + i][w] = dbits[i];
                dbits[i] = 0;
            }
        }
    }
    __syncwarp();

    int xlen = xl[b], ylen = yl[b];

    // ---- backtrack: run-length over bit words (lane 0) ----
    if (lane == 0) {
        int idx = xlen - 1;
        int yy  = ylen - 1;
        while (yy >= 0) {
            if (idx == 0) { s_dr[0] += yy + 1; break; }
            int yw = yy >> 5;
            unsigned mask = ((yy & 31) == 31) ? 0xffffffffu
                                              : ((2u << (yy & 31)) - 1u);
            unsigned m = s_diagT[idx][yw] & mask;
            if (m) {
                int ystar = (yw << 5) + (31 - __clz(m));
                s_dr[idx] += yy - ystar + 1;
                idx--;
                yy = ystar - 1;
            } else {
                s_dr[idx] += yy - (yw << 5) + 1;
                yy = (yw << 5) - 1;
            }
        }
    }
    __syncwarp();

    // ---- exclusive cumsum of durations (warp scan) ----
    int t[8], run[8];
    int tot = 0;
    #pragma unroll
    for (int i = 0; i < 8; i++) {
        t[i] = s_dr[lane * 8 + i];
        tot += t[i];
        run[i] = tot;                 // local inclusive
    }
    int sc = tot;
    #pragma unroll
    for (int d = 1; d < 32; d <<= 1) {
        int n = __shfl_up_sync(0xffffffffu, sc, d);
        if (lane >= d) sc += n;
    }
    int excl = sc - tot;
    if (lane == 0) s_cum[0] = 0;
    #pragma unroll
    for (int i = 0; i < 8; i++)
        s_cum[lane * 8 + i + 1] = excl + run[i];
    __syncwarp();

    // ---- g_idx via binary search (32 y per lane) + dr output ----
    #pragma unroll
    for (int k = 0; k < TY / 32; k++) {
        int yy = k * 32 + lane;
        int r = -1;
        if (yy < ylen) {
            int lo = 0, hi = TX - 1;
            #pragma unroll
            for (int s = 0; s < 8; s++) {
                int mid = (lo + hi) >> 1;
                if (yy >= s_cum[mid + 1]) lo = mid + 1; else hi = mid;
            }
            r = lo;
        }
        g_idx[b * TY + yy] = r;
    }
    #pragma unroll
    for (int i = 0; i < 8; i++)
        out[OFF_DR + b * TX + lane * 8 + i] = (float)s_dr[lane * 8 + i];
}

// =====================================================================
// K4: fused epilogue — attn one-hot + o_en gather, float4 stores
// =====================================================================
__global__ __launch_bounds__(256)
void k_epi(const float* __restrict__ en, float* __restrict__ out) {
    int bid = blockIdx.x;
    if (bid < 1024) {
        // attn: element range [b][x][y], 4 y per thread
        int e = (bid * 256 + threadIdx.x) * 4;
        int y4 = e & (TY - 1);
        int x  = (e >> 10) & (TX - 1);
        int b  = e >> 18;
        int4 id = *(const int4*)&g_idx[b * TY + y4];
        float4 r;
        r.x = (id.x == x) ? 1.0f : 0.0f;
        r.y = (id.y == x) ? 1.0f : 0.0f;
        r.z = (id.z == x) ? 1.0f : 0.0f;
        r.w = (id.w == x) ? 1.0f : 0.0f;
        *(float4*)&out[OFF_ATTN + e] = r;
    } else {
        // o_en_ex: element range [b][h][y], 4 y per thread
        int e = ((bid - 1024) * 256 + threadIdx.x) * 4;
        int y4 = e & (TY - 1);
        int h  = (e >> 10) & (HH - 1);
        int b  = e >> 18;
        int4 id = *(const int4*)&g_idx[b * TY + y4];
        const float* er = en + (b * HH + h) * TX;
        float4 r;
        r.x = (id.x >= 0) ? er[id.x] : 0.0f;
        r.y = (id.y >= 0) ? er[id.y] : 0.0f;
        r.z = (id.z >= 0) ? er[id.z] : 0.0f;
        r.w = (id.w >= 0) ? er[id.w] : 0.0f;
        *(float4*)&out[OFF_OEN + e] = r;
    }
}

// =====================================================================
extern "C" void kernel_launch(void* const* d_in, const int* in_sizes, int n_in,
                              void* d_out, int out_size) {
    const float* en = (const float*)d_in[0];
    const float* mu = (const float*)d_in[1];
    const float* ls = (const float*)d_in[2];
    const float* y  = (const float*)d_in[3];
    const int*   xl = (const int*)d_in[4];
    const int*   yl = (const int*)d_in[5];
    float* out = (float*)d_out;

    k_pre<<<BB, TX>>>(mu, ls);

    dim3 g2(TY / TSY, TX / TSX, BB);   // (16, 4, 4)
    k_logp<<<g2, 256>>>(y, xl, yl, out);

    k_dp<<<BB, 32>>>(xl, yl, out);

    k_epi<<<2048, 256>>>(en, out);
}

// round 3
// speedup vs baseline: 2.1946x; 1.2580x over previous
#include <cuda_runtime.h>
#include <cuda_bf16.h>
#include <cstdint>

#define BB 4
#define HH 256
#define CC 80
#define TX 256
#define TY 1024
#define NEGV (-1e9f)

// Output layout (float32):
//  o_en_ex [B,H,Ty]  -> offset 0
//  logp    [B,Tx,Ty] -> offset 1048576
//  attn    [B,Tx,Ty] -> offset 2097152
//  dr_mas  [B,Tx]    -> offset 3145728
#define OFF_OEN  0
#define OFF_LOGP 1048576
#define OFF_ATTN 2097152
#define OFF_DR   3145728

// -------- device scratch --------
__device__ float g_A  [BB*CC*TX];
__device__ float g_Bc [BB*CC*TX];
__device__ float g_cst[BB*TX];
__device__ float g_lpT[BB*TY*TX];   // masked logp, transposed [b][y][x]
__device__ int   g_idx[BB*TY];      // alignment index per y (-1 = inactive)

// =====================================================================
// K1: per-(b,x) channel precompute
// =====================================================================
__global__ void k_pre(const float* __restrict__ mu,
                      const float* __restrict__ ls) {
    int b = blockIdx.x;
    int x = threadIdx.x;
    float s3 = 0.f, sl = 0.f;
    #pragma unroll 4
    for (int c = 0; c < CC; c++) {
        int o = (b * CC + c) * TX + x;
        float l = ls[o];
        float m = mu[o];
        float w = expf(-2.0f * l);
        g_A [o] = (-0.5f / (float)CC) * w;
        g_Bc[o] = (1.0f / (float)CC) * w * m;
        s3 += w * m * m;
        sl += l;
    }
    g_cst[b * TX + x] = (-0.5f / (float)CC) * (s3 + sl);
}

// =====================================================================
// K2: logp GEMM  logp[b,x,y] = sum_c A*y^2 + B*y + cst
// =====================================================================
#define TSX 64
#define TSY 64
#define KCH 40

__global__ __launch_bounds__(256, 2)
void k_logp(const float* __restrict__ y,
            const int* __restrict__ xl,
            const int* __restrict__ yl,
            float* __restrict__ out) {
    __shared__ float sA [KCH][TSX];
    __shared__ float sB [KCH][TSX];
    __shared__ float sY [KCH][TSY];
    __shared__ float sY2[KCH][TSY];

    int b  = blockIdx.z;
    int x0 = blockIdx.y * TSX;
    int y0 = blockIdx.x * TSY;
    int tid = threadIdx.x;
    int ty = tid & 15;
    int tx = tid >> 4;
    int xr = tx * 4;
    int yc = ty * 4;

    float acc[4][4] = {};

    for (int kc = 0; kc < CC; kc += KCH) {
        __syncthreads();
        #pragma unroll
        for (int i = tid; i < KCH * TSX; i += 256) {
            int c = i >> 6, j = i & 63;
            int oa = (b * CC + (kc + c)) * TX + x0 + j;
            sA[c][j] = g_A[oa];
            sB[c][j] = g_Bc[oa];
            float yv = y[(b * CC + (kc + c)) * TY + y0 + j];
            sY [c][j] = yv;
            sY2[c][j] = yv * yv;
        }
        __syncthreads();

        #pragma unroll 8
        for (int c = 0; c < KCH; c++) {
            float4 a  = *(const float4*)&sA [c][xr];
            float4 bb = *(const float4*)&sB [c][xr];
            float4 yv = *(const float4*)&sY [c][yc];
            float4 y2 = *(const float4*)&sY2[c][yc];
            float av[4] = {a.x, a.y, a.z, a.w};
            float bv[4] = {bb.x, bb.y, bb.z, bb.w};
            float yvv[4] = {yv.x, yv.y, yv.z, yv.w};
            float y2v[4] = {y2.x, y2.y, y2.z, y2.w};
            #pragma unroll
            for (int i = 0; i < 4; i++)
                #pragma unroll
                for (int j = 0; j < 4; j++) {
                    acc[i][j] = fmaf(av[i], y2v[j], acc[i][j]);
                    acc[i][j] = fmaf(bv[i], yvv[j], acc[i][j]);
                }
        }
    }

    float cst_i[4];
    #pragma unroll
    for (int i = 0; i < 4; i++)
        cst_i[i] = g_cst[b * TX + x0 + xr + i];

    int xlen = xl[b], ylen = yl[b];

    #pragma unroll
    for (int i = 0; i < 4; i++) {
        int gx = x0 + xr + i;
        float4 r;
        r.x = acc[i][0] + cst_i[i];
        r.y = acc[i][1] + cst_i[i];
        r.z = acc[i][2] + cst_i[i];
        r.w = acc[i][3] + cst_i[i];
        *(float4*)&out[OFF_LOGP + ((size_t)(b * TX + gx)) * TY + y0 + yc] = r;
    }

    #pragma unroll
    for (int j = 0; j < 4; j++) {
        int gy = y0 + yc + j;
        bool ym = gy < ylen;
        float4 t;
        t.x = (ym && (x0 + xr + 0) < xlen) ? acc[0][j] + cst_i[0] : NEGV;
        t.y = (ym && (x0 + xr + 1) < xlen) ? acc[1][j] + cst_i[1] : NEGV;
        t.z = (ym && (x0 + xr + 2) < xlen) ? acc[2][j] + cst_i[2] : NEGV;
        t.w = (ym && (x0 + xr + 3) < xlen) ? acc[3][j] + cst_i[3] : NEGV;
        *(float4*)&g_lpT[((size_t)(b * TY + gy)) * TX + x0 + xr] = t;
    }
}

// =====================================================================
// K3: Viterbi DP — producer/consumer smem pipeline.
//   Warp 0: DP over x in registers (8 x per lane), 1 shfl/step.
//   Warps 1-3: stream 64-row chunks of g_lpT into 2-buffer smem ring.
//   Diag bits: diag[word][x] layout, conflict-free uint4 flush.
// =====================================================================
#define DPCHUNK 64
// dynamic smem layout (bytes):
//   rows: float4[2][64*64]      = 131072
//   diag: unsigned[32][256]     =  32768  @ 131072
//   dr:   int[256]              =   1024  @ 163840
//   cum:  int[257]              =   1028  @ 164864
#define DP_SMEM_BYTES 165896

__global__ __launch_bounds__(128, 1)
void k_dp(const int* __restrict__ xl,
          const int* __restrict__ yl,
          float* __restrict__ out) {
    extern __shared__ char smem[];
    float4*   rows  = (float4*)smem;                      // [2][4096]
    unsigned* diag  = (unsigned*)(smem + 131072);         // [32][256]
    int*      s_dr  = (int*)(smem + 163840);
    int*      s_cum = (int*)(smem + 164864);

    int b    = blockIdx.x;
    int tid  = threadIdx.x;
    int wid  = tid >> 5;
    int lane = tid & 31;

    int xlen = xl[b], ylen = yl[b];
    int nck  = (ylen + DPCHUNK - 1) / DPCHUNK;

    const float4* lp4 = (const float4*)(g_lpT + (size_t)b * TY * TX);

    // zero dr + prologue load of chunk 0 (all threads)
    s_dr[tid] = 0; s_dr[tid + 128] = 0;
    for (int i = tid; i < 4096; i += 128) rows[i] = lp4[i];
    __syncthreads();

    if (wid == 0) {
        float v[8];
        #pragma unroll
        for (int i = 0; i < 8; i++) v[i] = NEGV;
        if (lane == 0) v[0] = 0.0f;

        for (int ck = 0; ck < nck; ck++) {
            const float4* rb = rows + (ck & 1) * 4096;
            float4 c0 = rb[lane * 2];
            float4 c1 = rb[lane * 2 + 1];

            for (int half = 0; half < 2; half++) {
                unsigned db[8] = {0,0,0,0,0,0,0,0};
                unsigned bit = 1u;
                for (int g = 0; g < 4; g++) {
                    #pragma unroll
                    for (int p = 0; p < 8; p++) {
                        int r  = half * 32 + g * 8 + p;
                        int rn = (r < 63) ? r + 1 : 63;
                        float4 n0 = rb[rn * 64 + lane * 2];
                        float4 n1 = rb[rn * 64 + lane * 2 + 1];

                        float top = __shfl_up_sync(0xffffffffu, v[7], 1);
                        if (lane == 0) top = NEGV;

                        float c[8] = {c0.x, c0.y, c0.z, c0.w,
                                      c1.x, c1.y, c1.z, c1.w};
                        #pragma unroll
                        for (int i = 7; i >= 1; i--) {
                            if (v[i - 1] > v[i]) db[i] |= bit;
                            v[i] = c[i] + fmaxf(v[i], v[i - 1]);
                        }
                        if (top > v[0]) db[0] |= bit;
                        v[0] = c[0] + fmaxf(v[0], top);

                        bit <<= 1;
                        c0 = n0; c1 = n1;
                    }
                }
                int w = ck * 2 + half;
                uint4 lo = make_uint4(db[0], db[1], db[2], db[3]);
                uint4 hi = make_uint4(db[4], db[5], db[6], db[7]);
                *(uint4*)&diag[w * 256 + lane * 8]     = lo;
                *(uint4*)&diag[w * 256 + lane * 8 + 4] = hi;
            }
            __syncthreads();     // pair with producers' chunk completion
        }
    } else {
        // producers: warps 1..3 (96 threads) stream chunk ck+1
        int pt = tid - 32;
        for (int ck = 0; ck < nck; ck++) {
            if (ck + 1 < nck) {
                const float4* src = lp4 + (ck + 1) * 4096;
                float4* dst = rows + ((ck + 1) & 1) * 4096;
                for (int i = pt; i < 4096; i += 96)
                    dst[i] = src[i];
            }
            __syncthreads();
        }
    }
    __syncthreads();

    // ---- backtrack: run-length over diag words (warp0 lane0) ----
    if (tid == 0) {
        int idx = xlen - 1;
        int yy  = ylen - 1;
        while (yy >= 0) {
            if (idx == 0) { s_dr[0] += yy + 1; break; }
            int yw = yy >> 5;
            unsigned mask = ((yy & 31) == 31) ? 0xffffffffu
                                              : ((2u << (yy & 31)) - 1u);
            unsigned m = diag[yw * 256 + idx] & mask;
            if (m) {
                int ystar = (yw << 5) + (31 - __clz(m));
                s_dr[idx] += yy - ystar + 1;
                idx--;
                yy = ystar - 1;
            } else {
                s_dr[idx] += yy - (yw << 5) + 1;
                yy = (yw << 5) - 1;
            }
        }
    }
    __syncthreads();

    // ---- exclusive cumsum of durations (warp 0) ----
    if (wid == 0) {
        int t[8], run[8];
        int tot = 0;
        #pragma unroll
        for (int i = 0; i < 8; i++) {
            t[i] = s_dr[lane * 8 + i];
            tot += t[i];
            run[i] = tot;
        }
        int sc = tot;
        #pragma unroll
        for (int d = 1; d < 32; d <<= 1) {
            int n = __shfl_up_sync(0xffffffffu, sc, d);
            if (lane >= d) sc += n;
        }
        int excl = sc - tot;
        if (lane == 0) s_cum[0] = 0;
        #pragma unroll
        for (int i = 0; i < 8; i++)
            s_cum[lane * 8 + i + 1] = excl + run[i];

        #pragma unroll
        for (int i = 0; i < 8; i++)
            out[OFF_DR + b * TX + lane * 8 + i] = (float)t[i];
    }
    __syncthreads();

    // ---- g_idx via binary search (8 y per thread) ----
    #pragma unroll
    for (int k = 0; k < TY / 128; k++) {
        int yy = k * 128 + tid;
        int r = -1;
        if (yy < ylen) {
            int lo = 0, hi = TX - 1;
            #pragma unroll
            for (int s = 0; s < 8; s++) {
                int mid = (lo + hi) >> 1;
                if (yy >= s_cum[mid + 1]) lo = mid + 1; else hi = mid;
            }
            r = lo;
        }
        g_idx[b * TY + yy] = r;
    }
}

// =====================================================================
// K4: fused epilogue — attn one-hot + o_en gather, float4 stores
// =====================================================================
__global__ __launch_bounds__(256)
void k_epi(const float* __restrict__ en, float* __restrict__ out) {
    int bid = blockIdx.x;
    if (bid < 1024) {
        int e = (bid * 256 + threadIdx.x) * 4;
        int y4 = e & (TY - 1);
        int x  = (e >> 10) & (TX - 1);
        int b  = e >> 18;
        int4 id = *(const int4*)&g_idx[b * TY + y4];
        float4 r;
        r.x = (id.x == x) ? 1.0f : 0.0f;
        r.y = (id.y == x) ? 1.0f : 0.0f;
        r.z = (id.z == x) ? 1.0f : 0.0f;
        r.w = (id.w == x) ? 1.0f : 0.0f;
        *(float4*)&out[OFF_ATTN + e] = r;
    } else {
        int e = ((bid - 1024) * 256 + threadIdx.x) * 4;
        int y4 = e & (TY - 1);
        int h  = (e >> 10) & (HH - 1);
        int b  = e >> 18;
        int4 id = *(const int4*)&g_idx[b * TY + y4];
        const float* er = en + (b * HH + h) * TX;
        float4 r;
        r.x = (id.x >= 0) ? er[id.x] : 0.0f;
        r.y = (id.y >= 0) ? er[id.y] : 0.0f;
        r.z = (id.z >= 0) ? er[id.z] : 0.0f;
        r.w = (id.w >= 0) ? er[id.w] : 0.0f;
        *(float4*)&out[OFF_OEN + e] = r;
    }
}

// =====================================================================
extern "C" void kernel_launch(void* const* d_in, const int* in_sizes, int n_in,
                              void* d_out, int out_size) {
    const float* en = (const float*)d_in[0];
    const float* mu = (const float*)d_in[1];
    const float* ls = (const float*)d_in[2];
    const float* y  = (const float*)d_in[3];
    const int*   xl = (const int*)d_in[4];
    const int*   yl = (const int*)d_in[5];
    float* out = (float*)d_out;

    cudaFuncSetAttribute(k_dp, cudaFuncAttributeMaxDynamicSharedMemorySize,
                         DP_SMEM_BYTES);

    k_pre<<<BB, TX>>>(mu, ls);

    dim3 g2(TY / TSY, TX / TSX, BB);   // (16, 4, 4)
    k_logp<<<g2, 256>>>(y, xl, yl, out);

    k_dp<<<BB, 128, DP_SMEM_BYTES>>>(xl, yl, out);

    k_epi<<<2048, 256>>>(en, out);
}

// round 4
// speedup vs baseline: 2.6657x; 1.2147x over previous
#include <cuda_runtime.h>
#include <cuda_bf16.h>
#include <cstdint>

#define BB 4
#define HH 256
#define CC 80
#define TX 256
#define TY 1024
#define NEGV (-1e9f)

// Output layout (float32):
//  o_en_ex [B,H,Ty]  -> offset 0
//  logp    [B,Tx,Ty] -> offset 1048576
//  attn    [B,Tx,Ty] -> offset 2097152
//  dr_mas  [B,Tx]    -> offset 3145728
#define OFF_OEN  0
#define OFF_LOGP 1048576
#define OFF_ATTN 2097152
#define OFF_DR   3145728

// -------- device scratch --------
__device__ float g_A  [BB*CC*TX];
__device__ float g_Bc [BB*CC*TX];
__device__ float g_cst[BB*TX];
__device__ float g_lpT[BB*TY*TX];   // masked logp, transposed [b][y][x]
__device__ int   g_idx[BB*TY];      // alignment index per y (-1 = inactive)

__device__ __forceinline__ void cp_async16(void* smem_dst, const void* gmem_src) {
    unsigned sa = (unsigned)__cvta_generic_to_shared(smem_dst);
    asm volatile("cp.async.cg.shared.global [%0], [%1], 16;\n"
                 :: "r"(sa), "l"(gmem_src));
}
__device__ __forceinline__ void cp_async_commit_wait() {
    asm volatile("cp.async.commit_group;\n");
    asm volatile("cp.async.wait_group 0;\n");
}

// =====================================================================
// K1: per-(b,x) channel precompute
// =====================================================================
__global__ void k_pre(const float* __restrict__ mu,
                      const float* __restrict__ ls) {
    int b = blockIdx.x;
    int x = threadIdx.x;
    float s3 = 0.f, sl = 0.f;
    #pragma unroll 4
    for (int c = 0; c < CC; c++) {
        int o = (b * CC + c) * TX + x;
        float l = ls[o];
        float m = mu[o];
        float w = expf(-2.0f * l);
        g_A [o] = (-0.5f / (float)CC) * w;
        g_Bc[o] = (1.0f / (float)CC) * w * m;
        s3 += w * m * m;
        sl += l;
    }
    g_cst[b * TX + x] = (-0.5f / (float)CC) * (s3 + sl);
}

// =====================================================================
// K2: logp GEMM  logp[b,x,y] = sum_c A*y^2 + B*y + cst
// =====================================================================
#define TSX 64
#define TSY 64
#define KCH 40

__global__ __launch_bounds__(256, 2)
void k_logp(const float* __restrict__ y,
            const int* __restrict__ xl,
            const int* __restrict__ yl,
            float* __restrict__ out) {
    __shared__ float sA [KCH][TSX];
    __shared__ float sB [KCH][TSX];
    __shared__ float sY [KCH][TSY];
    __shared__ float sY2[KCH][TSY];

    int b  = blockIdx.z;
    int x0 = blockIdx.y * TSX;
    int y0 = blockIdx.x * TSY;
    int tid = threadIdx.x;
    int ty = tid & 15;
    int tx = tid >> 4;
    int xr = tx * 4;
    int yc = ty * 4;

    float acc[4][4] = {};

    for (int kc = 0; kc < CC; kc += KCH) {
        __syncthreads();
        #pragma unroll
        for (int i = tid; i < KCH * TSX; i += 256) {
            int c = i >> 6, j = i & 63;
            int oa = (b * CC + (kc + c)) * TX + x0 + j;
            sA[c][j] = g_A[oa];
            sB[c][j] = g_Bc[oa];
            float yv = y[(b * CC + (kc + c)) * TY + y0 + j];
            sY [c][j] = yv;
            sY2[c][j] = yv * yv;
        }
        __syncthreads();

        #pragma unroll 8
        for (int c = 0; c < KCH; c++) {
            float4 a  = *(const float4*)&sA [c][xr];
            float4 bb = *(const float4*)&sB [c][xr];
            float4 yv = *(const float4*)&sY [c][yc];
            float4 y2 = *(const float4*)&sY2[c][yc];
            float av[4] = {a.x, a.y, a.z, a.w};
            float bv[4] = {bb.x, bb.y, bb.z, bb.w};
            float yvv[4] = {yv.x, yv.y, yv.z, yv.w};
            float y2v[4] = {y2.x, y2.y, y2.z, y2.w};
            #pragma unroll
            for (int i = 0; i < 4; i++)
                #pragma unroll
                for (int j = 0; j < 4; j++) {
                    acc[i][j] = fmaf(av[i], y2v[j], acc[i][j]);
                    acc[i][j] = fmaf(bv[i], yvv[j], acc[i][j]);
                }
        }
    }

    float cst_i[4];
    #pragma unroll
    for (int i = 0; i < 4; i++)
        cst_i[i] = g_cst[b * TX + x0 + xr + i];

    int xlen = xl[b], ylen = yl[b];

    #pragma unroll
    for (int i = 0; i < 4; i++) {
        int gx = x0 + xr + i;
        float4 r;
        r.x = acc[i][0] + cst_i[i];
        r.y = acc[i][1] + cst_i[i];
        r.z = acc[i][2] + cst_i[i];
        r.w = acc[i][3] + cst_i[i];
        *(float4*)&out[OFF_LOGP + ((size_t)(b * TX + gx)) * TY + y0 + yc] = r;
    }

    #pragma unroll
    for (int j = 0; j < 4; j++) {
        int gy = y0 + yc + j;
        bool ym = gy < ylen;
        float4 t;
        t.x = (ym && (x0 + xr + 0) < xlen) ? acc[0][j] + cst_i[0] : NEGV;
        t.y = (ym && (x0 + xr + 1) < xlen) ? acc[1][j] + cst_i[1] : NEGV;
        t.z = (ym && (x0 + xr + 2) < xlen) ? acc[2][j] + cst_i[2] : NEGV;
        t.w = (ym && (x0 + xr + 3) < xlen) ? acc[3][j] + cst_i[3] : NEGV;
        *(float4*)&g_lpT[((size_t)(b * TY + gy)) * TX + x0 + xr] = t;
    }
}

// =====================================================================
// K3: Viterbi DP — producer/consumer smem pipeline, cp.async producers.
// =====================================================================
#define DPCHUNK 64
// dynamic smem layout (bytes):
//   rows: float4[2][64*64] = 131072
//   diag: unsigned[32][256] = 32768 @ 131072
//   dr:   int[256]          @ 163840
//   cum:  int[257]          @ 164864
#define DP_SMEM_BYTES 165896

__global__ __launch_bounds__(128, 1)
void k_dp(const int* __restrict__ xl,
          const int* __restrict__ yl,
          float* __restrict__ out) {
    extern __shared__ char smem[];
    float4*   rows  = (float4*)smem;                      // [2][4096]
    unsigned* diag  = (unsigned*)(smem + 131072);         // [32][256]
    int*      s_dr  = (int*)(smem + 163840);
    int*      s_cum = (int*)(smem + 164864);

    int b    = blockIdx.x;
    int tid  = threadIdx.x;
    int wid  = tid >> 5;
    int lane = tid & 31;

    int xlen = xl[b], ylen = yl[b];
    int nck  = (ylen + DPCHUNK - 1) / DPCHUNK;

    const float4* lp4 = (const float4*)(g_lpT + (size_t)b * TY * TX);

    // zero dr + async prologue load of chunk 0 (all threads)
    s_dr[tid] = 0; s_dr[tid + 128] = 0;
    for (int i = tid; i < 4096; i += 128)
        cp_async16(rows + i, lp4 + i);
    cp_async_commit_wait();
    __syncthreads();

    if (wid == 0) {
        float v[8];
        #pragma unroll
        for (int i = 0; i < 8; i++) v[i] = NEGV;
        if (lane == 0) v[0] = 0.0f;

        for (int ck = 0; ck < nck; ck++) {
            const float4* rb = rows + (ck & 1) * 4096;
            float4 c0 = rb[lane * 2];
            float4 c1 = rb[lane * 2 + 1];

            for (int half = 0; half < 2; half++) {
                unsigned db[8] = {0,0,0,0,0,0,0,0};
                unsigned bit = 1u;
                for (int g = 0; g < 4; g++) {
                    #pragma unroll
                    for (int p = 0; p < 8; p++) {
                        int r  = half * 32 + g * 8 + p;
                        int rn = (r < 63) ? r + 1 : 63;
                        float4 n0 = rb[rn * 64 + lane * 2];
                        float4 n1 = rb[rn * 64 + lane * 2 + 1];

                        float top = __shfl_up_sync(0xffffffffu, v[7], 1);
                        if (lane == 0) top = NEGV;

                        float c[8] = {c0.x, c0.y, c0.z, c0.w,
                                      c1.x, c1.y, c1.z, c1.w};
                        #pragma unroll
                        for (int i = 7; i >= 1; i--) {
                            if (v[i - 1] > v[i]) db[i] |= bit;
                            v[i] = c[i] + fmaxf(v[i], v[i - 1]);
                        }
                        if (top > v[0]) db[0] |= bit;
                        v[0] = c[0] + fmaxf(v[0], top);

                        bit <<= 1;
                        c0 = n0; c1 = n1;
                    }
                }
                int w = ck * 2 + half;
                uint4 lo = make_uint4(db[0], db[1], db[2], db[3]);
                uint4 hi = make_uint4(db[4], db[5], db[6], db[7]);
                *(uint4*)&diag[w * 256 + lane * 8]     = lo;
                *(uint4*)&diag[w * 256 + lane * 8 + 4] = hi;
            }
            __syncthreads();     // pair with producers' chunk completion
        }
    } else {
        // producers: warps 1..3 (96 threads) stream chunk ck+1 via cp.async
        int pt = tid - 32;
        for (int ck = 0; ck < nck; ck++) {
            if (ck + 1 < nck) {
                const float4* src = lp4 + (ck + 1) * 4096;
                float4* dst = rows + ((ck + 1) & 1) * 4096;
                for (int i = pt; i < 4096; i += 96)
                    cp_async16(dst + i, src + i);
                cp_async_commit_wait();
            }
            __syncthreads();
        }
    }
    __syncthreads();

    // ---- backtrack: run-length over diag words (warp0 lane0) ----
    if (tid == 0) {
        int idx = xlen - 1;
        int yy  = ylen - 1;
        while (yy >= 0) {
            if (idx == 0) { s_dr[0] += yy + 1; break; }
            int yw = yy >> 5;
            unsigned mask = ((yy & 31) == 31) ? 0xffffffffu
                                              : ((2u << (yy & 31)) - 1u);
            unsigned m = diag[yw * 256 + idx] & mask;
            if (m) {
                int ystar = (yw << 5) + (31 - __clz(m));
                s_dr[idx] += yy - ystar + 1;
                idx--;
                yy = ystar - 1;
            } else {
                s_dr[idx] += yy - (yw << 5) + 1;
                yy = (yw << 5) - 1;
            }
        }
    }
    __syncthreads();

    // ---- exclusive cumsum of durations (warp 0) ----
    if (wid == 0) {
        int t[8], run[8];
        int tot = 0;
        #pragma unroll
        for (int i = 0; i < 8; i++) {
            t[i] = s_dr[lane * 8 + i];
            tot += t[i];
            run[i] = tot;
        }
        int sc = tot;
        #pragma unroll
        for (int d = 1; d < 32; d <<= 1) {
            int n = __shfl_up_sync(0xffffffffu, sc, d);
            if (lane >= d) sc += n;
        }
        int excl = sc - tot;
        if (lane == 0) s_cum[0] = 0;
        #pragma unroll
        for (int i = 0; i < 8; i++)
            s_cum[lane * 8 + i + 1] = excl + run[i];

        #pragma unroll
        for (int i = 0; i < 8; i++)
            out[OFF_DR + b * TX + lane * 8 + i] = (float)t[i];
    }
    __syncthreads();

    // ---- g_idx via binary search (8 y per thread) ----
    #pragma unroll
    for (int k = 0; k < TY / 128; k++) {
        int yy = k * 128 + tid;
        int r = -1;
        if (yy < ylen) {
            int lo = 0, hi = TX - 1;
            #pragma unroll
            for (int s = 0; s < 8; s++) {
                int mid = (lo + hi) >> 1;
                if (yy >= s_cum[mid + 1]) lo = mid + 1; else hi = mid;
            }
            r = lo;
        }
        g_idx[b * TY + yy] = r;
    }
}

// =====================================================================
// K4: fused epilogue — one block per output row (uniform b/x/h per block)
// =====================================================================
__global__ __launch_bounds__(256)
void k_epi(const float* __restrict__ en, float* __restrict__ out) {
    int bid = blockIdx.x;
    int tid = threadIdx.x;
    if (bid < BB * TX) {
        // attn row (b, x): 256 threads x 4 y
        int b = bid >> 8, x = bid & 255;
        int4 id = *(const int4*)&g_idx[b * TY + tid * 4];
        float4 r;
        r.x = (id.x == x) ? 1.0f : 0.0f;
        r.y = (id.y == x) ? 1.0f : 0.0f;
        r.z = (id.z == x) ? 1.0f : 0.0f;
        r.w = (id.w == x) ? 1.0f : 0.0f;
        *(float4*)&out[OFF_ATTN + (size_t)bid * TY + tid * 4] = r;
    } else {
        // o_en_ex row (b, h): stage en row in smem, gather 4 y per thread
        __shared__ float se[TX];
        int rb = bid - BB * TX;
        int b = rb >> 8, h = rb & 255;
        if (tid < TX / 4)
            *(float4*)&se[tid * 4] = *(const float4*)&en[(b * HH + h) * TX + tid * 4];
        __syncthreads();
        int4 id = *(const int4*)&g_idx[b * TY + tid * 4];
        float4 r;
        r.x = (id.x >= 0) ? se[id.x] : 0.0f;
        r.y = (id.y >= 0) ? se[id.y] : 0.0f;
        r.z = (id.z >= 0) ? se[id.z] : 0.0f;
        r.w = (id.w >= 0) ? se[id.w] : 0.0f;
        *(float4*)&out[OFF_OEN + (size_t)rb * TY + tid * 4] = r;
    }
}

// =====================================================================
extern "C" void kernel_launch(void* const* d_in, const int* in_sizes, int n_in,
                              void* d_out, int out_size) {
    const float* en = (const float*)d_in[0];
    const float* mu = (const float*)d_in[1];
    const float* ls = (const float*)d_in[2];
    const float* y  = (const float*)d_in[3];
    const int*   xl = (const int*)d_in[4];
    const int*   yl = (const int*)d_in[5];
    float* out = (float*)d_out;

    cudaFuncSetAttribute(k_dp, cudaFuncAttributeMaxDynamicSharedMemorySize,
                         DP_SMEM_BYTES);

    k_pre<<<BB, TX>>>(mu, ls);

    dim3 g2(TY / TSY, TX / TSX, BB);   // (16, 4, 4)
    k_logp<<<g2, 256>>>(y, xl, yl, out);

    k_dp<<<BB, 128, DP_SMEM_BYTES>>>(xl, yl, out);

    k_epi<<<2 * BB * TX, 256>>>(en, out);
}